// round 2
// baseline (speedup 1.0000x reference)
#include <cuda_runtime.h>
#include <cstdint>
#include <math.h>

#define BB 2
#define NQ 1024
#define NKV 2048
#define DM 1024
#define NH 16
#define DH 64
#define SCALE 0.125f
#define LNEPS 1e-5f

// ---------------- scratch (alloc-free rule: __device__ globals) ----------------
__device__ float g_qn[BB * NQ * DM];        // 8 MB
__device__ float g_kvn[BB * NKV * DM];      // 16 MB
__device__ float g_Q[BB * NQ * NH * DH];    // 8 MB
__device__ float g_K[BB * NKV * NH * DH];   // 16 MB
__device__ float g_V[BB * NKV * NH * DH];   // 16 MB
__device__ float g_ctx[BB * NQ * NH * DH];  // 8 MB
__device__ float g_mask[BB * NKV];          // normalized mask (1.0 = keep)
__device__ float g_attn_fallback[(size_t)BB * NH * NQ * NKV]; // 256 MB fallback

// ---------------- mask normalization: dtype-agnostic (bool/int32/float32) ------
__global__ void mask_kernel(const unsigned char* __restrict__ m) {
    __shared__ int s_ge2, s_off;
    int t = threadIdx.x;
    if (t == 0) { s_ge2 = 0; s_off = 0; }
    __syncthreads();
    int ge2 = 0, off = 0;
    for (int i = t; i < BB * NKV; i += 256) {
        unsigned char b = m[i];               // first 4096 bytes: safe for any dtype
        if (b >= 2) ge2 = 1;
        if ((i & 3) && b) off = 1;
    }
    if (ge2) atomicOr(&s_ge2, 1);
    if (off) atomicOr(&s_off, 1);
    __syncthreads();
    int kind = s_ge2 ? 2 : (s_off ? 0 : 1);   // 2=float32, 1=int32, 0=uint8/bool
    for (int i = t; i < BB * NKV; i += 256) {
        float v;
        if (kind == 2)       v = (((const float*)m)[i] != 0.0f) ? 1.0f : 0.0f;
        else if (kind == 1)  v = (((const int*)m)[i] != 0) ? 1.0f : 0.0f;
        else                 v = (m[i] != 0) ? 1.0f : 0.0f;
        g_mask[i] = v;
    }
}

// ---------------- LayerNorm: one block per row of 1024 ----------------
__global__ void ln_kernel(const float* __restrict__ q, const float* __restrict__ kv,
                          const float* __restrict__ gam, const float* __restrict__ bet) {
    __shared__ float red[256];
    int row = blockIdx.x;
    const float* src;
    float* dst;
    if (row < BB * NQ) { src = q + (size_t)row * DM; dst = g_qn + (size_t)row * DM; }
    else { int r = row - BB * NQ; src = kv + (size_t)r * DM; dst = g_kvn + (size_t)r * DM; }
    int t = threadIdx.x;
    float4 x = ((const float4*)src)[t];
    red[t] = x.x + x.y + x.z + x.w;
    __syncthreads();
    for (int o = 128; o > 0; o >>= 1) { if (t < o) red[t] += red[t + o]; __syncthreads(); }
    float mu = red[0] * (1.0f / DM);
    __syncthreads();
    float dx = x.x - mu, dy = x.y - mu, dz = x.z - mu, dw = x.w - mu;
    red[t] = dx * dx + dy * dy + dz * dz + dw * dw;
    __syncthreads();
    for (int o = 128; o > 0; o >>= 1) { if (t < o) red[t] += red[t + o]; __syncthreads(); }
    float rstd = rsqrtf(red[0] * (1.0f / DM) + LNEPS);
    float4 g4 = ((const float4*)gam)[t];
    float4 b4 = ((const float4*)bet)[t];
    float4 o4;
    o4.x = dx * rstd * g4.x + b4.x;
    o4.y = dy * rstd * g4.y + b4.y;
    o4.z = dz * rstd * g4.z + b4.z;
    o4.w = dw * rstd * g4.w + b4.w;
    ((float4*)dst)[t] = o4;
}

// ---------------- SGEMM 128x128x8, 8x8 per thread: C[M,1024]=A[M,1024]@W[1024,1024]+bias ----
__global__ __launch_bounds__(256) void sgemm_bias_kernel(
    const float* __restrict__ A, const float* __restrict__ W,
    const float* __restrict__ bias, float* __restrict__ C) {
    __shared__ float As[8][128]; // [k][m]
    __shared__ float Bs[8][128]; // [k][n]
    int t = threadIdx.x;
    int tx = t & 15, ty = t >> 4;
    int n0 = blockIdx.x * 128, m0 = blockIdx.y * 128;
    int ar = t >> 1, ac = (t & 1) * 4;
    int br = t >> 5, bc = (t & 31) * 4;
    float acc[8][8];
#pragma unroll
    for (int i = 0; i < 8; i++)
#pragma unroll
        for (int j = 0; j < 8; j++) acc[i][j] = 0.0f;
    for (int k0 = 0; k0 < DM; k0 += 8) {
        float4 a4 = *(const float4*)(A + (size_t)(m0 + ar) * DM + k0 + ac);
        As[ac + 0][ar] = a4.x; As[ac + 1][ar] = a4.y; As[ac + 2][ar] = a4.z; As[ac + 3][ar] = a4.w;
        *(float4*)&Bs[br][bc] = *(const float4*)(W + (size_t)(k0 + br) * DM + n0 + bc);
        __syncthreads();
#pragma unroll
        for (int c = 0; c < 8; c++) {
            float a[8], b[8];
            *(float4*)(a) = *(const float4*)&As[c][ty * 8];
            *(float4*)(a + 4) = *(const float4*)&As[c][ty * 8 + 4];
            *(float4*)(b) = *(const float4*)&Bs[c][tx * 8];
            *(float4*)(b + 4) = *(const float4*)&Bs[c][tx * 8 + 4];
#pragma unroll
            for (int i = 0; i < 8; i++)
#pragma unroll
                for (int j = 0; j < 8; j++) acc[i][j] += a[i] * b[j];
        }
        __syncthreads();
    }
#pragma unroll
    for (int i = 0; i < 8; i++) {
        int m = m0 + ty * 8 + i;
#pragma unroll
        for (int j = 0; j < 8; j += 4) {
            int n = n0 + tx * 8 + j;
            float4 o;
            o.x = acc[i][j + 0] + bias[n + 0];
            o.y = acc[i][j + 1] + bias[n + 1];
            o.z = acc[i][j + 2] + bias[n + 2];
            o.w = acc[i][j + 3] + bias[n + 3];
            *(float4*)(C + (size_t)m * DM + n) = o;
        }
    }
}

// ---------------- QK^T scores (per bh), 128x128 tile over d=64, mask -> -inf ---------------
__global__ __launch_bounds__(256) void qk_kernel(float* __restrict__ attn) {
    __shared__ float As[8][128]; // [d][q]
    __shared__ float Bs[8][128]; // [d][k]
    int bh = blockIdx.z;
    int b = bh >> 4, h = bh & 15;
    int q0 = blockIdx.y * 128, k0 = blockIdx.x * 128;
    int t = threadIdx.x;
    int tx = t & 15, ty = t >> 4;
    int ar = t >> 1, ac = (t & 1) * 4;
    float acc[8][8];
#pragma unroll
    for (int i = 0; i < 8; i++)
#pragma unroll
        for (int j = 0; j < 8; j++) acc[i][j] = 0.0f;
    for (int c0 = 0; c0 < DH; c0 += 8) {
        float4 qa = *(const float4*)(g_Q + (size_t)(b * NQ + q0 + ar) * (NH * DH) + h * DH + c0 + ac);
        As[ac + 0][ar] = qa.x; As[ac + 1][ar] = qa.y; As[ac + 2][ar] = qa.z; As[ac + 3][ar] = qa.w;
        float4 ka = *(const float4*)(g_K + (size_t)(b * NKV + k0 + ar) * (NH * DH) + h * DH + c0 + ac);
        Bs[ac + 0][ar] = ka.x; Bs[ac + 1][ar] = ka.y; Bs[ac + 2][ar] = ka.z; Bs[ac + 3][ar] = ka.w;
        __syncthreads();
#pragma unroll
        for (int c = 0; c < 8; c++) {
            float a[8], bb[8];
            *(float4*)(a) = *(const float4*)&As[c][ty * 8];
            *(float4*)(a + 4) = *(const float4*)&As[c][ty * 8 + 4];
            *(float4*)(bb) = *(const float4*)&Bs[c][tx * 8];
            *(float4*)(bb + 4) = *(const float4*)&Bs[c][tx * 8 + 4];
#pragma unroll
            for (int i = 0; i < 8; i++)
#pragma unroll
                for (int j = 0; j < 8; j++) acc[i][j] += a[i] * bb[j];
        }
        __syncthreads();
    }
#pragma unroll
    for (int i = 0; i < 8; i++) {
        int qq = q0 + ty * 8 + i;
        float* orow = attn + ((size_t)bh * NQ + qq) * NKV;
#pragma unroll
        for (int j = 0; j < 8; j++) {
            int kk = k0 + tx * 8 + j;
            float v = (g_mask[b * NKV + kk] != 0.0f) ? acc[i][j] * SCALE : -INFINITY;
            orow[kk] = v;
        }
    }
}

// ---------------- RPE add: block = (q, k-tile of 128); rpe tile read ONCE, reused by 32 bh ---
__global__ __launch_bounds__(128) void rpe_kernel(const float* __restrict__ rpe,
                                                  float* __restrict__ attn) {
    __shared__ float Rp[64][128]; // d-major, XOR-swizzled 16B chunks: 32 KB
    __shared__ float Qs[32][68];  // [bh][d], padded: ~8.7 KB
    int q = blockIdx.y;
    int k0 = blockIdx.x * 128;
    int t = threadIdx.x;
    // fill Rp (coalesced global read, swizzled transpose store)
    const float4* gr = (const float4*)(rpe + ((size_t)q * NKV + k0) * DH);
#pragma unroll
    for (int s = 0; s < 16; s++) {
        int f = s * 128 + t; // float4 index over 128x64 tile (k-major in gmem)
        float4 v = gr[f];
        int kk = f >> 4;  // 0..127
        int dv = f & 15;  // float4 along d
        int g = kk >> 2, l = kk & 3;
        float vv[4] = {v.x, v.y, v.z, v.w};
#pragma unroll
        for (int j = 0; j < 4; j++) {
            int dd = dv * 4 + j;
            int gs = g ^ ((dd >> 2) & 7);
            Rp[dd][gs * 4 + l] = vv[j];
        }
    }
    // fill Qs: Q[b, q, h, :] for all 32 bh
#pragma unroll
    for (int s = 0; s < 4; s++) {
        int f = s * 128 + t; // float4 index over 32x64
        int bh = f >> 4, dv = f & 15;
        int b = bh >> 4, h = bh & 15;
        float4 v = *(const float4*)(g_Q + (size_t)(b * NQ + q) * (NH * DH) + h * DH + dv * 4);
        *(float4*)&Qs[bh][dv * 4] = v;
    }
    __syncthreads();
    int tx = t & 31;  // k chunk lane (4 k's)
    int ty = t >> 5;  // bh group (8 bh's)
    float acc[8][4];
#pragma unroll
    for (int j = 0; j < 8; j++)
#pragma unroll
        for (int i = 0; i < 4; i++) acc[j][i] = 0.0f;
#pragma unroll 4
    for (int d = 0; d < 64; d++) {
        int gs = (d >> 2) & 7;
        float4 rv = *(const float4*)&Rp[d][(tx ^ gs) * 4];
#pragma unroll
        for (int j = 0; j < 8; j++) {
            float qv = Qs[ty * 8 + j][d];
            acc[j][0] += qv * rv.x;
            acc[j][1] += qv * rv.y;
            acc[j][2] += qv * rv.z;
            acc[j][3] += qv * rv.w;
        }
    }
#pragma unroll
    for (int j = 0; j < 8; j++) {
        int bh = ty * 8 + j;
        float* p = attn + ((size_t)bh * NQ + q) * NKV + k0 + tx * 4;
        float4 cur = *(float4*)p;
        cur.x += SCALE * acc[j][0];
        cur.y += SCALE * acc[j][1];
        cur.z += SCALE * acc[j][2];
        cur.w += SCALE * acc[j][3];
        *(float4*)p = cur;
    }
}

// ---------------- in-place softmax over last dim (2048), one block per row ----------------
__global__ void softmax_kernel(float* __restrict__ attn) {
    __shared__ float red[256];
    size_t row = blockIdx.x;
    float4* p = (float4*)(attn + row * (size_t)NKV);
    int t = threadIdx.x;
    float4 v1 = p[t], v2 = p[t + 256];
    float m = fmaxf(fmaxf(fmaxf(v1.x, v1.y), fmaxf(v1.z, v1.w)),
                    fmaxf(fmaxf(v2.x, v2.y), fmaxf(v2.z, v2.w)));
    red[t] = m;
    __syncthreads();
    for (int o = 128; o > 0; o >>= 1) { if (t < o) red[t] = fmaxf(red[t], red[t + o]); __syncthreads(); }
    float M = red[0];
    __syncthreads();
    v1.x = __expf(v1.x - M); v1.y = __expf(v1.y - M); v1.z = __expf(v1.z - M); v1.w = __expf(v1.w - M);
    v2.x = __expf(v2.x - M); v2.y = __expf(v2.y - M); v2.z = __expf(v2.z - M); v2.w = __expf(v2.w - M);
    float s = v1.x + v1.y + v1.z + v1.w + v2.x + v2.y + v2.z + v2.w;
    red[t] = s;
    __syncthreads();
    for (int o = 128; o > 0; o >>= 1) { if (t < o) red[t] += red[t + o]; __syncthreads(); }
    float inv = 1.0f / red[0];
    v1.x *= inv; v1.y *= inv; v1.z *= inv; v1.w *= inv;
    v2.x *= inv; v2.y *= inv; v2.z *= inv; v2.w *= inv;
    p[t] = v1;
    p[t + 256] = v2;
}

// ---------------- AV: per bh GEMM [1024 x 2048] @ [2048 x 64] -> ctx ----------------
__global__ __launch_bounds__(256) void av_kernel(const float* __restrict__ attn) {
    __shared__ float As[16][128]; // [k][q]
    __shared__ float Bs[16][64];  // [k][d]
    int bh = blockIdx.y;
    int b = bh >> 4, h = bh & 15;
    int q0 = blockIdx.x * 128;
    int t = threadIdx.x;
    int tx = t & 15, ty = t >> 4;
    const float* Abase = attn + (size_t)bh * NQ * NKV;
    float acc[8][4];
#pragma unroll
    for (int j = 0; j < 8; j++)
#pragma unroll
        for (int i = 0; i < 4; i++) acc[j][i] = 0.0f;
    for (int k0 = 0; k0 < NKV; k0 += 16) {
#pragma unroll
        for (int s = 0; s < 2; s++) {
            int f = s * 256 + t; // float4 index over 128x16 tile
            int r = f >> 2;
            int v = f & 3;
            float4 a4 = *(const float4*)(Abase + (size_t)(q0 + r) * NKV + k0 + v * 4);
            As[v * 4 + 0][r] = a4.x; As[v * 4 + 1][r] = a4.y;
            As[v * 4 + 2][r] = a4.z; As[v * 4 + 3][r] = a4.w;
        }
        {
            int kr = t >> 4, dv = t & 15;
            *(float4*)&Bs[kr][dv * 4] =
                *(const float4*)(g_V + (size_t)(b * NKV + k0 + kr) * (NH * DH) + h * DH + dv * 4);
        }
        __syncthreads();
#pragma unroll
        for (int c = 0; c < 16; c++) {
            float a[8], bb[4];
            *(float4*)(a) = *(const float4*)&As[c][ty * 8];
            *(float4*)(a + 4) = *(const float4*)&As[c][ty * 8 + 4];
            *(float4*)(bb) = *(const float4*)&Bs[c][tx * 4];
#pragma unroll
            for (int j = 0; j < 8; j++)
#pragma unroll
                for (int i = 0; i < 4; i++) acc[j][i] += a[j] * bb[i];
        }
        __syncthreads();
    }
#pragma unroll
    for (int j = 0; j < 8; j++) {
        float4 o;
        o.x = acc[j][0]; o.y = acc[j][1]; o.z = acc[j][2]; o.w = acc[j][3];
        *(float4*)(g_ctx + (size_t)(b * NQ + q0 + ty * 8 + j) * (NH * DH) + h * DH + tx * 4) = o;
    }
}

// ---------------- launch ----------------
extern "C" void kernel_launch(void* const* d_in, const int* in_sizes, int n_in,
                              void* d_out, int out_size) {
    const float* q = (const float*)d_in[0];
    const float* kv = (const float*)d_in[1];
    const unsigned char* mask = (const unsigned char*)d_in[2];
    const float* rpe = (const float*)d_in[3];
    const float* Wq = (const float*)d_in[4];
    const float* bq = (const float*)d_in[5];
    const float* Wk = (const float*)d_in[6];
    const float* bk = (const float*)d_in[7];
    const float* Wv = (const float*)d_in[8];
    const float* bv = (const float*)d_in[9];
    const float* Wo = (const float*)d_in[10];
    const float* bo = (const float*)d_in[11];
    const float* lg = (const float*)d_in[12];
    const float* lb = (const float*)d_in[13];

    float* out = (float*)d_out;
    const size_t ATT = (size_t)BB * NH * NQ * NKV;       // 67108864
    const size_t OUTN = (size_t)BB * NQ * DM;            // 2097152
    float* attn;
    if ((size_t)out_size >= ATT + OUTN) {
        attn = out + ((size_t)out_size - ATT);           // tuple (out, atten) flattened
    } else {
        void* p;
        cudaGetSymbolAddress(&p, g_attn_fallback);
        attn = (float*)p;
    }

    float *p_qn, *p_kvn, *p_Q, *p_K, *p_V, *p_ctx;
    { void* p; cudaGetSymbolAddress(&p, g_qn); p_qn = (float*)p; }
    { void* p; cudaGetSymbolAddress(&p, g_kvn); p_kvn = (float*)p; }
    { void* p; cudaGetSymbolAddress(&p, g_Q); p_Q = (float*)p; }
    { void* p; cudaGetSymbolAddress(&p, g_K); p_K = (float*)p; }
    { void* p; cudaGetSymbolAddress(&p, g_V); p_V = (float*)p; }
    { void* p; cudaGetSymbolAddress(&p, g_ctx); p_ctx = (float*)p; }

    mask_kernel<<<1, 256>>>(mask);
    ln_kernel<<<BB * NQ + BB * NKV, 256>>>(q, kv, lg, lb);

    dim3 gq(DM / 128, (BB * NQ) / 128);   // 8 x 16
    dim3 gkv(DM / 128, (BB * NKV) / 128); // 8 x 32
    sgemm_bias_kernel<<<gq, 256>>>(p_qn, Wq, bq, p_Q);
    sgemm_bias_kernel<<<gkv, 256>>>(p_kvn, Wk, bk, p_K);
    sgemm_bias_kernel<<<gkv, 256>>>(p_kvn, Wv, bv, p_V);

    qk_kernel<<<dim3(NKV / 128, NQ / 128, BB * NH), 256>>>(attn);
    rpe_kernel<<<dim3(NKV / 128, NQ), 128>>>(rpe, attn);
    softmax_kernel<<<BB * NH * NQ, 256>>>(attn);
    av_kernel<<<dim3(NQ / 128, BB * NH), 256>>>(attn);

    sgemm_bias_kernel<<<gq, 256>>>(p_ctx, Wo, bo, out);
}

// round 4
// speedup vs baseline: 1.3514x; 1.3514x over previous
#include <cuda_runtime.h>
#include <cuda_bf16.h>
#include <cstdint>
#include <math.h>

#define BB 2
#define NQ 1024
#define NKV 2048
#define DM 1024
#define NH 16
#define DH 64
#define SCALE 0.125f
#define LNEPS 1e-5f

// ================= scratch (alloc-free rule: __device__ globals) ================
__device__ __nv_bfloat16 g_qnh[BB * NQ * DM], g_qnl[BB * NQ * DM];
__device__ __nv_bfloat16 g_kvnh[BB * NKV * DM], g_kvnl[BB * NKV * DM];
__device__ __nv_bfloat16 g_Wqh[DM * DM], g_Wql[DM * DM];
__device__ __nv_bfloat16 g_Wkh[DM * DM], g_Wkl[DM * DM];
__device__ __nv_bfloat16 g_Wvh[DM * DM], g_Wvl[DM * DM];
__device__ __nv_bfloat16 g_Woh[DM * DM], g_Wol[DM * DM];
__device__ __nv_bfloat16 g_ctxh[BB * NQ * NH * DH], g_ctxl[BB * NQ * NH * DH];
__device__ float g_Q[BB * NQ * NH * DH];
__device__ float g_K[BB * NKV * NH * DH];
__device__ float g_V[BB * NKV * NH * DH];
__device__ float g_ctx[BB * NQ * NH * DH];
__device__ float g_mask[BB * NKV];
__device__ float g_attn_fallback[(size_t)BB * NH * NQ * NKV];

__device__ __forceinline__ void split_bf16(float x, __nv_bfloat16& h, __nv_bfloat16& l) {
    h = __float2bfloat16_rn(x);
    l = __float2bfloat16_rn(x - __bfloat162float(h));
}
__device__ __forceinline__ uint32_t smem_u32(const void* p) {
    uint32_t a;
    asm("{ .reg .u64 t; cvta.to.shared.u64 t, %1; cvt.u32.u64 %0, t; }" : "=r"(a) : "l"(p));
    return a;
}
__device__ __forceinline__ void ldsm4(uint32_t* d, uint32_t addr) {
    asm volatile("ldmatrix.sync.aligned.m8n8.x4.shared.b16 {%0,%1,%2,%3}, [%4];"
                 : "=r"(d[0]), "=r"(d[1]), "=r"(d[2]), "=r"(d[3]) : "r"(addr));
}
__device__ __forceinline__ void mma16816(float* c, const uint32_t* a, uint32_t b0, uint32_t b1) {
    asm volatile("mma.sync.aligned.m16n8k16.row.col.f32.bf16.bf16.f32 "
                 "{%0,%1,%2,%3}, {%4,%5,%6,%7}, {%8,%9}, {%0,%1,%2,%3};"
                 : "+f"(c[0]), "+f"(c[1]), "+f"(c[2]), "+f"(c[3])
                 : "r"(a[0]), "r"(a[1]), "r"(a[2]), "r"(a[3]), "r"(b0), "r"(b1));
}

// ---------------- mask normalization: dtype-agnostic (bool/int32/float32) ------
__global__ void mask_kernel(const unsigned char* __restrict__ m) {
    __shared__ int s_ge2, s_off;
    int t = threadIdx.x;
    if (t == 0) { s_ge2 = 0; s_off = 0; }
    __syncthreads();
    int ge2 = 0, off = 0;
    for (int i = t; i < BB * NKV; i += 256) {
        unsigned char b = m[i];
        if (b >= 2) ge2 = 1;
        if ((i & 3) && b) off = 1;
    }
    if (ge2) atomicOr(&s_ge2, 1);
    if (off) atomicOr(&s_off, 1);
    __syncthreads();
    int kind = s_ge2 ? 2 : (s_off ? 0 : 1);
    for (int i = t; i < BB * NKV; i += 256) {
        float v;
        if (kind == 2)      v = (((const float*)m)[i] != 0.0f) ? 1.0f : 0.0f;
        else if (kind == 1) v = (((const int*)m)[i] != 0) ? 1.0f : 0.0f;
        else                v = (m[i] != 0) ? 1.0f : 0.0f;
        g_mask[i] = v;
    }
}

// ---------------- LayerNorm -> bf16 hi/lo ----------------
__global__ void ln_kernel(const float* __restrict__ q, const float* __restrict__ kv,
                          const float* __restrict__ gam, const float* __restrict__ bet) {
    __shared__ float red[256];
    int row = blockIdx.x;
    const float* src;
    __nv_bfloat16 *dh, *dl;
    if (row < BB * NQ) {
        src = q + (size_t)row * DM;
        dh = g_qnh + (size_t)row * DM; dl = g_qnl + (size_t)row * DM;
    } else {
        int r = row - BB * NQ;
        src = kv + (size_t)r * DM;
        dh = g_kvnh + (size_t)r * DM; dl = g_kvnl + (size_t)r * DM;
    }
    int t = threadIdx.x;
    float4 x = ((const float4*)src)[t];
    red[t] = x.x + x.y + x.z + x.w;
    __syncthreads();
    for (int o = 128; o > 0; o >>= 1) { if (t < o) red[t] += red[t + o]; __syncthreads(); }
    float mu = red[0] * (1.0f / DM);
    __syncthreads();
    float dx = x.x - mu, dy = x.y - mu, dz = x.z - mu, dw = x.w - mu;
    red[t] = dx * dx + dy * dy + dz * dz + dw * dw;
    __syncthreads();
    for (int o = 128; o > 0; o >>= 1) { if (t < o) red[t] += red[t + o]; __syncthreads(); }
    float rstd = rsqrtf(red[0] * (1.0f / DM) + LNEPS);
    float4 g4 = ((const float4*)gam)[t];
    float4 b4 = ((const float4*)bet)[t];
    float o0 = dx * rstd * g4.x + b4.x;
    float o1 = dy * rstd * g4.y + b4.y;
    float o2 = dz * rstd * g4.z + b4.z;
    float o3 = dw * rstd * g4.w + b4.w;
    __nv_bfloat16 h[4], l[4];
    split_bf16(o0, h[0], l[0]); split_bf16(o1, h[1], l[1]);
    split_bf16(o2, h[2], l[2]); split_bf16(o3, h[3], l[3]);
    *(uint2*)(dh + 4 * t) = *(uint2*)h;
    *(uint2*)(dl + 4 * t) = *(uint2*)l;
}

// ---------------- weight transpose + bf16 split: W[k][n] -> T{h,l}[n][k] --------
__global__ void wconv_kernel(const float* __restrict__ W,
                             __nv_bfloat16* __restrict__ Th, __nv_bfloat16* __restrict__ Tl) {
    __shared__ float tile[32][33];
    int bx = blockIdx.x * 32;  // n
    int by = blockIdx.y * 32;  // k
    int tx = threadIdx.x, ty = threadIdx.y;
#pragma unroll
    for (int i = 0; i < 32; i += 8)
        tile[ty + i][tx] = W[(size_t)(by + ty + i) * DM + bx + tx];
    __syncthreads();
#pragma unroll
    for (int i = 0; i < 32; i += 8) {
        float v = tile[tx][ty + i];   // k = by+tx, n = bx+ty+i
        __nv_bfloat16 h, l;
        split_bf16(v, h, l);
        Th[(size_t)(bx + ty + i) * DM + by + tx] = h;
        Tl[(size_t)(bx + ty + i) * DM + by + tx] = l;
    }
}

// ---------------- ctx fp32 -> bf16 hi/lo ----------------
__global__ void ctxconv_kernel() {
    int i = blockIdx.x * 256 + threadIdx.x;
    float v = g_ctx[i];
    __nv_bfloat16 h, l;
    split_bf16(v, h, l);
    g_ctxh[i] = h; g_ctxl[i] = l;
}

// ================= HMMA GEMM: C[M,1024] = (Ah+Al)@(Bh+Bl)^T + bias =================
// A row-major [M][1024] bf16; B = W^T stored [n][k] bf16. 3 products in fp32 acc.
// Block 128x128, K-chunk 64, 8 warps (2m x 4n), warp tile 64x32.
#define GS_AH 0
#define GS_AL 16384
#define GS_BH 32768
#define GS_BL 49152
#define GS_TOTAL 65536

__global__ __launch_bounds__(256, 2) void gemm_mma(
    const __nv_bfloat16* __restrict__ Ah, const __nv_bfloat16* __restrict__ Al,
    const __nv_bfloat16* __restrict__ Bh, const __nv_bfloat16* __restrict__ Bl,
    const float* __restrict__ bias, float* __restrict__ C) {
    extern __shared__ char smem[];
    uint32_t sb = smem_u32(smem);
    int t = threadIdx.x, lane = t & 31, wid = t >> 5;
    int wm = wid & 1, wn = wid >> 1;
    int m0 = blockIdx.y * 128, n0 = blockIdx.x * 128;

    float acc[4][4][4];
#pragma unroll
    for (int i = 0; i < 4; i++)
#pragma unroll
        for (int j = 0; j < 4; j++)
#pragma unroll
            for (int k = 0; k < 4; k++) acc[i][j][k] = 0.0f;

    for (int kt = 0; kt < 16; kt++) {
        int kg = kt * 64;
        if (kt > 0) __syncthreads();
#pragma unroll
        for (int i = 0; i < 4; i++) {
            int id = i * 256 + t;           // 0..1023 16B chunks
            int r = id >> 3, c8 = id & 7;
            uint32_t off = (uint32_t)(r * 128 + ((c8 ^ (r & 7)) << 4));
            *(uint4*)(smem + GS_AH + off) = *(const uint4*)(Ah + (size_t)(m0 + r) * DM + kg + c8 * 8);
            *(uint4*)(smem + GS_AL + off) = *(const uint4*)(Al + (size_t)(m0 + r) * DM + kg + c8 * 8);
            *(uint4*)(smem + GS_BH + off) = *(const uint4*)(Bh + (size_t)(n0 + r) * DM + kg + c8 * 8);
            *(uint4*)(smem + GS_BL + off) = *(const uint4*)(Bl + (size_t)(n0 + r) * DM + kg + c8 * 8);
        }
        __syncthreads();
#pragma unroll
        for (int ks = 0; ks < 4; ks++) {
            int c0 = ks * 2;
            uint32_t bh[2][4], bl[2][4];
#pragma unroll
            for (int j = 0; j < 2; j++) {
                int rowb = wn * 32 + j * 16 + (lane & 15);
                int ch = c0 + (lane >> 4);
                uint32_t so = (uint32_t)(rowb * 128 + ((ch ^ (rowb & 7)) << 4));
                ldsm4(bh[j], sb + GS_BH + so);
                ldsm4(bl[j], sb + GS_BL + so);
            }
#pragma unroll
            for (int mi = 0; mi < 4; mi++) {
                int rowa = wm * 64 + mi * 16 + (lane & 15);
                int ch = c0 + (lane >> 4);
                uint32_t so = (uint32_t)(rowa * 128 + ((ch ^ (rowa & 7)) << 4));
                uint32_t ah[4], al[4];
                ldsm4(ah, sb + GS_AH + so);
                ldsm4(al, sb + GS_AL + so);
#pragma unroll
                for (int ni = 0; ni < 4; ni++) {
                    int j = ni >> 1, s = ni & 1;
                    uint32_t b0h = bh[j][s], b1h = bh[j][s + 2];
                    uint32_t b0l = bl[j][s], b1l = bl[j][s + 2];
                    mma16816(acc[mi][ni], ah, b0h, b1h);
                    mma16816(acc[mi][ni], ah, b0l, b1l);
                    mma16816(acc[mi][ni], al, b0h, b1h);
                }
            }
        }
    }

#pragma unroll
    for (int mi = 0; mi < 4; mi++) {
#pragma unroll
        for (int ni = 0; ni < 4; ni++) {
            int m = m0 + wm * 64 + mi * 16 + (lane >> 2);
            int n = n0 + wn * 32 + ni * 8 + (lane & 3) * 2;
            float2 bv = *(const float2*)(bias + n);
            float2 v0 = make_float2(acc[mi][ni][0] + bv.x, acc[mi][ni][1] + bv.y);
            float2 v1 = make_float2(acc[mi][ni][2] + bv.x, acc[mi][ni][3] + bv.y);
            *(float2*)(C + (size_t)m * DM + n) = v0;
            *(float2*)(C + (size_t)(m + 8) * DM + n) = v1;
        }
    }
}

// ---------------- QK^T scores (per bh), 128x128 tile over d=64, mask -> -inf ---------------
__global__ __launch_bounds__(256) void qk_kernel(float* __restrict__ attn) {
    __shared__ float As[8][128];
    __shared__ float Bs[8][128];
    int bh = blockIdx.z;
    int b = bh >> 4, h = bh & 15;
    int q0 = blockIdx.y * 128, k0 = blockIdx.x * 128;
    int t = threadIdx.x;
    int tx = t & 15, ty = t >> 4;
    int ar = t >> 1, ac = (t & 1) * 4;
    float acc[8][8];
#pragma unroll
    for (int i = 0; i < 8; i++)
#pragma unroll
        for (int j = 0; j < 8; j++) acc[i][j] = 0.0f;
    for (int c0 = 0; c0 < DH; c0 += 8) {
        float4 qa = *(const float4*)(g_Q + (size_t)(b * NQ + q0 + ar) * (NH * DH) + h * DH + c0 + ac);
        As[ac + 0][ar] = qa.x; As[ac + 1][ar] = qa.y; As[ac + 2][ar] = qa.z; As[ac + 3][ar] = qa.w;
        float4 ka = *(const float4*)(g_K + (size_t)(b * NKV + k0 + ar) * (NH * DH) + h * DH + c0 + ac);
        Bs[ac + 0][ar] = ka.x; Bs[ac + 1][ar] = ka.y; Bs[ac + 2][ar] = ka.z; Bs[ac + 3][ar] = ka.w;
        __syncthreads();
#pragma unroll
        for (int c = 0; c < 8; c++) {
            float a[8], bb[8];
            *(float4*)(a) = *(const float4*)&As[c][ty * 8];
            *(float4*)(a + 4) = *(const float4*)&As[c][ty * 8 + 4];
            *(float4*)(bb) = *(const float4*)&Bs[c][tx * 8];
            *(float4*)(bb + 4) = *(const float4*)&Bs[c][tx * 8 + 4];
#pragma unroll
            for (int i = 0; i < 8; i++)
#pragma unroll
                for (int j = 0; j < 8; j++) acc[i][j] += a[i] * bb[j];
        }
        __syncthreads();
    }
#pragma unroll
    for (int i = 0; i < 8; i++) {
        int qq = q0 + ty * 8 + i;
        float* orow = attn + ((size_t)bh * NQ + qq) * NKV;
#pragma unroll
        for (int j = 0; j < 8; j++) {
            int kk = k0 + tx * 8 + j;
            float v = (g_mask[b * NKV + kk] != 0.0f) ? acc[i][j] * SCALE : -INFINITY;
            orow[kk] = v;
        }
    }
}

// ---------------- RPE add ----------------
__global__ __launch_bounds__(128) void rpe_kernel(const float* __restrict__ rpe,
                                                  float* __restrict__ attn) {
    __shared__ float Rp[64][128];
    __shared__ float Qs[32][68];
    int q = blockIdx.y;
    int k0 = blockIdx.x * 128;
    int t = threadIdx.x;
    const float4* gr = (const float4*)(rpe + ((size_t)q * NKV + k0) * DH);
#pragma unroll
    for (int s = 0; s < 16; s++) {
        int f = s * 128 + t;
        float4 v = gr[f];
        int kk = f >> 4;
        int dv = f & 15;
        int g = kk >> 2, l = kk & 3;
        float vv[4] = {v.x, v.y, v.z, v.w};
#pragma unroll
        for (int j = 0; j < 4; j++) {
            int dd = dv * 4 + j;
            int gs = g ^ ((dd >> 2) & 7);
            Rp[dd][gs * 4 + l] = vv[j];
        }
    }
#pragma unroll
    for (int s = 0; s < 4; s++) {
        int f = s * 128 + t;
        int bh = f >> 4, dv = f & 15;
        int b = bh >> 4, h = bh & 15;
        float4 v = *(const float4*)(g_Q + (size_t)(b * NQ + q) * (NH * DH) + h * DH + dv * 4);
        *(float4*)&Qs[bh][dv * 4] = v;
    }
    __syncthreads();
    int tx = t & 31;
    int ty = t >> 5;
    float acc[8][4];
#pragma unroll
    for (int j = 0; j < 8; j++)
#pragma unroll
        for (int i = 0; i < 4; i++) acc[j][i] = 0.0f;
#pragma unroll 4
    for (int d = 0; d < 64; d++) {
        int gs = (d >> 2) & 7;
        float4 rv = *(const float4*)&Rp[d][(tx ^ gs) * 4];
#pragma unroll
        for (int j = 0; j < 8; j++) {
            float qv = Qs[ty * 8 + j][d];
            acc[j][0] += qv * rv.x;
            acc[j][1] += qv * rv.y;
            acc[j][2] += qv * rv.z;
            acc[j][3] += qv * rv.w;
        }
    }
#pragma unroll
    for (int j = 0; j < 8; j++) {
        int bh = ty * 8 + j;
        float* p = attn + ((size_t)bh * NQ + q) * NKV + k0 + tx * 4;
        float4 cur = *(float4*)p;
        cur.x += SCALE * acc[j][0];
        cur.y += SCALE * acc[j][1];
        cur.z += SCALE * acc[j][2];
        cur.w += SCALE * acc[j][3];
        *(float4*)p = cur;
    }
}

// ---------------- in-place softmax ----------------
__global__ void softmax_kernel(float* __restrict__ attn) {
    __shared__ float red[256];
    size_t row = blockIdx.x;
    float4* p = (float4*)(attn + row * (size_t)NKV);
    int t = threadIdx.x;
    float4 v1 = p[t], v2 = p[t + 256];
    float m = fmaxf(fmaxf(fmaxf(v1.x, v1.y), fmaxf(v1.z, v1.w)),
                    fmaxf(fmaxf(v2.x, v2.y), fmaxf(v2.z, v2.w)));
    red[t] = m;
    __syncthreads();
    for (int o = 128; o > 0; o >>= 1) { if (t < o) red[t] = fmaxf(red[t], red[t + o]); __syncthreads(); }
    float M = red[0];
    __syncthreads();
    v1.x = __expf(v1.x - M); v1.y = __expf(v1.y - M); v1.z = __expf(v1.z - M); v1.w = __expf(v1.w - M);
    v2.x = __expf(v2.x - M); v2.y = __expf(v2.y - M); v2.z = __expf(v2.z - M); v2.w = __expf(v2.w - M);
    float s = v1.x + v1.y + v1.z + v1.w + v2.x + v2.y + v2.z + v2.w;
    red[t] = s;
    __syncthreads();
    for (int o = 128; o > 0; o >>= 1) { if (t < o) red[t] += red[t + o]; __syncthreads(); }
    float inv = 1.0f / red[0];
    v1.x *= inv; v1.y *= inv; v1.z *= inv; v1.w *= inv;
    v2.x *= inv; v2.y *= inv; v2.z *= inv; v2.w *= inv;
    p[t] = v1;
    p[t + 256] = v2;
}

// ---------------- AV ----------------
__global__ __launch_bounds__(256) void av_kernel(const float* __restrict__ attn) {
    __shared__ float As[16][128];
    __shared__ float Bs[16][64];
    int bh = blockIdx.y;
    int b = bh >> 4, h = bh & 15;
    int q0 = blockIdx.x * 128;
    int t = threadIdx.x;
    int tx = t & 15, ty = t >> 4;
    const float* Abase = attn + (size_t)bh * NQ * NKV;
    float acc[8][4];
#pragma unroll
    for (int j = 0; j < 8; j++)
#pragma unroll
        for (int i = 0; i < 4; i++) acc[j][i] = 0.0f;
    for (int k0 = 0; k0 < NKV; k0 += 16) {
#pragma unroll
        for (int s = 0; s < 2; s++) {
            int f = s * 256 + t;
            int r = f >> 2;
            int v = f & 3;
            float4 a4 = *(const float4*)(Abase + (size_t)(q0 + r) * NKV + k0 + v * 4);
            As[v * 4 + 0][r] = a4.x; As[v * 4 + 1][r] = a4.y;
            As[v * 4 + 2][r] = a4.z; As[v * 4 + 3][r] = a4.w;
        }
        {
            int kr = t >> 4, dv = t & 15;
            *(float4*)&Bs[kr][dv * 4] =
                *(const float4*)(g_V + (size_t)(b * NKV + k0 + kr) * (NH * DH) + h * DH + dv * 4);
        }
        __syncthreads();
#pragma unroll
        for (int c = 0; c < 16; c++) {
            float a[8], bb[4];
            *(float4*)(a) = *(const float4*)&As[c][ty * 8];
            *(float4*)(a + 4) = *(const float4*)&As[c][ty * 8 + 4];
            *(float4*)(bb) = *(const float4*)&Bs[c][tx * 4];
#pragma unroll
            for (int j = 0; j < 8; j++)
#pragma unroll
                for (int i = 0; i < 4; i++) acc[j][i] += a[j] * bb[i];
        }
        __syncthreads();
    }
#pragma unroll
    for (int j = 0; j < 8; j++) {
        float4 o;
        o.x = acc[j][0]; o.y = acc[j][1]; o.z = acc[j][2]; o.w = acc[j][3];
        *(float4*)(g_ctx + (size_t)(b * NQ + q0 + ty * 8 + j) * (NH * DH) + h * DH + tx * 4) = o;
    }
}

// ---------------- launch ----------------
extern "C" void kernel_launch(void* const* d_in, const int* in_sizes, int n_in,
                              void* d_out, int out_size) {
    const float* q = (const float*)d_in[0];
    const float* kv = (const float*)d_in[1];
    const unsigned char* mask = (const unsigned char*)d_in[2];
    const float* rpe = (const float*)d_in[3];
    const float* Wq = (const float*)d_in[4];
    const float* bq = (const float*)d_in[5];
    const float* Wk = (const float*)d_in[6];
    const float* bk = (const float*)d_in[7];
    const float* Wv = (const float*)d_in[8];
    const float* bv = (const float*)d_in[9];
    const float* Wo = (const float*)d_in[10];
    const float* bo = (const float*)d_in[11];
    const float* lg = (const float*)d_in[12];
    const float* lb = (const float*)d_in[13];

    float* out = (float*)d_out;
    const size_t ATT = (size_t)BB * NH * NQ * NKV;
    const size_t OUTN = (size_t)BB * NQ * DM;
    float* attn;
    if ((size_t)out_size >= ATT + OUTN) {
        attn = out + ((size_t)out_size - ATT);
    } else {
        void* p;
        cudaGetSymbolAddress(&p, g_attn_fallback);
        attn = (float*)p;
    }

#define SYMF(sym) ([]{ void* p; cudaGetSymbolAddress(&p, sym); return (float*)p; }())
#define SYMB(sym) ([]{ void* p; cudaGetSymbolAddress(&p, sym); return (__nv_bfloat16*)p; }())
    float* p_Q = SYMF(g_Q);
    float* p_K = SYMF(g_K);
    float* p_V = SYMF(g_V);
    float* p_ctx = SYMF(g_ctx);
    __nv_bfloat16* p_qnh = SYMB(g_qnh);   __nv_bfloat16* p_qnl = SYMB(g_qnl);
    __nv_bfloat16* p_kvnh = SYMB(g_kvnh); __nv_bfloat16* p_kvnl = SYMB(g_kvnl);
    __nv_bfloat16* p_Wqh = SYMB(g_Wqh);   __nv_bfloat16* p_Wql = SYMB(g_Wql);
    __nv_bfloat16* p_Wkh = SYMB(g_Wkh);   __nv_bfloat16* p_Wkl = SYMB(g_Wkl);
    __nv_bfloat16* p_Wvh = SYMB(g_Wvh);   __nv_bfloat16* p_Wvl = SYMB(g_Wvl);
    __nv_bfloat16* p_Woh = SYMB(g_Woh);   __nv_bfloat16* p_Wol = SYMB(g_Wol);
    __nv_bfloat16* p_ctxh = SYMB(g_ctxh); __nv_bfloat16* p_ctxl = SYMB(g_ctxl);

    cudaFuncSetAttribute(gemm_mma, cudaFuncAttributeMaxDynamicSharedMemorySize, GS_TOTAL);

    mask_kernel<<<1, 256>>>(mask);
    ln_kernel<<<BB * NQ + BB * NKV, 256>>>(q, kv, lg, lb);

    dim3 wt(32, 8);
    dim3 wg(32, 32);
    wconv_kernel<<<wg, wt>>>(Wq, p_Wqh, p_Wql);
    wconv_kernel<<<wg, wt>>>(Wk, p_Wkh, p_Wkl);
    wconv_kernel<<<wg, wt>>>(Wv, p_Wvh, p_Wvl);
    wconv_kernel<<<wg, wt>>>(Wo, p_Woh, p_Wol);

    gemm_mma<<<dim3(8, 16), 256, GS_TOTAL>>>(p_qnh, p_qnl, p_Wqh, p_Wql, bq, p_Q);
    gemm_mma<<<dim3(8, 32), 256, GS_TOTAL>>>(p_kvnh, p_kvnl, p_Wkh, p_Wkl, bk, p_K);
    gemm_mma<<<dim3(8, 32), 256, GS_TOTAL>>>(p_kvnh, p_kvnl, p_Wvh, p_Wvl, bv, p_V);

    qk_kernel<<<dim3(NKV / 128, NQ / 128, BB * NH), 256>>>(attn);
    rpe_kernel<<<dim3(NKV / 128, NQ), 128>>>(rpe, attn);
    softmax_kernel<<<BB * NH * NQ, 256>>>(attn);
    av_kernel<<<dim3(NQ / 128, BB * NH), 256>>>(attn);

    ctxconv_kernel<<<(BB * NQ * NH * DH) / 256, 256>>>();
    gemm_mma<<<dim3(8, 16), 256, GS_TOTAL>>>(p_ctxh, p_ctxl, p_Woh, p_Wol, bo, out);
}

// round 5
// speedup vs baseline: 2.1246x; 1.5721x over previous
#include <cuda_runtime.h>
#include <cuda_bf16.h>
#include <cstdint>
#include <math.h>

#define BB 2
#define NQ 1024
#define NKV 2048
#define DM 1024
#define NH 16
#define DH 64
#define SCALE 0.125f
#define LNEPS 1e-5f

// ================= scratch (alloc-free rule: __device__ globals) ================
__device__ __nv_bfloat16 g_qnh[BB * NQ * DM], g_qnl[BB * NQ * DM];
__device__ __nv_bfloat16 g_kvnh[BB * NKV * DM], g_kvnl[BB * NKV * DM];
__device__ __nv_bfloat16 g_Wqh[DM * DM], g_Wql[DM * DM];
__device__ __nv_bfloat16 g_Wkh[DM * DM], g_Wkl[DM * DM];
__device__ __nv_bfloat16 g_Wvh[DM * DM], g_Wvl[DM * DM];
__device__ __nv_bfloat16 g_Woh[DM * DM], g_Wol[DM * DM];
__device__ __nv_bfloat16 g_ctxh[BB * NQ * NH * DH], g_ctxl[BB * NQ * NH * DH];
__device__ __nv_bfloat16 g_Qh[BB * NQ * DM], g_Ql[BB * NQ * DM];
__device__ __nv_bfloat16 g_Kh[BB * NKV * DM], g_Kl[BB * NKV * DM];
__device__ __nv_bfloat16 g_Vth[BB * NH * DH * NKV], g_Vtl[BB * NH * DH * NKV]; // [bh][d][kv]
__device__ __nv_bfloat16 g_ah[(size_t)BB * NH * NQ * NKV];  // attn probs hi
__device__ __nv_bfloat16 g_al[(size_t)BB * NH * NQ * NKV];  // attn probs lo
__device__ float g_Q[BB * NQ * NH * DH];
__device__ float g_V[BB * NKV * NH * DH];
__device__ float g_ctx[BB * NQ * NH * DH];
__device__ float g_mask[BB * NKV];
__device__ float g_attn_fallback[(size_t)BB * NH * NQ * NKV];

__device__ __forceinline__ void split_bf16(float x, __nv_bfloat16& h, __nv_bfloat16& l) {
    h = __float2bfloat16_rn(x);
    l = __float2bfloat16_rn(x - __bfloat162float(h));
}
__device__ __forceinline__ uint32_t smem_u32(const void* p) {
    uint32_t a;
    asm("{ .reg .u64 t; cvta.to.shared.u64 t, %1; cvt.u32.u64 %0, t; }" : "=r"(a) : "l"(p));
    return a;
}
__device__ __forceinline__ void ldsm4(uint32_t* d, uint32_t addr) {
    asm volatile("ldmatrix.sync.aligned.m8n8.x4.shared.b16 {%0,%1,%2,%3}, [%4];"
                 : "=r"(d[0]), "=r"(d[1]), "=r"(d[2]), "=r"(d[3]) : "r"(addr));
}
__device__ __forceinline__ void mma16816(float* c, const uint32_t* a, uint32_t b0, uint32_t b1) {
    asm volatile("mma.sync.aligned.m16n8k16.row.col.f32.bf16.bf16.f32 "
                 "{%0,%1,%2,%3}, {%4,%5,%6,%7}, {%8,%9}, {%0,%1,%2,%3};"
                 : "+f"(c[0]), "+f"(c[1]), "+f"(c[2]), "+f"(c[3])
                 : "r"(a[0]), "r"(a[1]), "r"(a[2]), "r"(a[3]), "r"(b0), "r"(b1));
}

// ---------------- mask normalization: dtype-agnostic ------
__global__ void mask_kernel(const unsigned char* __restrict__ m) {
    __shared__ int s_ge2, s_off;
    int t = threadIdx.x;
    if (t == 0) { s_ge2 = 0; s_off = 0; }
    __syncthreads();
    int ge2 = 0, off = 0;
    for (int i = t; i < BB * NKV; i += 256) {
        unsigned char b = m[i];
        if (b >= 2) ge2 = 1;
        if ((i & 3) && b) off = 1;
    }
    if (ge2) atomicOr(&s_ge2, 1);
    if (off) atomicOr(&s_off, 1);
    __syncthreads();
    int kind = s_ge2 ? 2 : (s_off ? 0 : 1);
    for (int i = t; i < BB * NKV; i += 256) {
        float v;
        if (kind == 2)      v = (((const float*)m)[i] != 0.0f) ? 1.0f : 0.0f;
        else if (kind == 1) v = (((const int*)m)[i] != 0) ? 1.0f : 0.0f;
        else                v = (m[i] != 0) ? 1.0f : 0.0f;
        g_mask[i] = v;
    }
}

// ---------------- LayerNorm -> bf16 hi/lo ----------------
__global__ void ln_kernel(const float* __restrict__ q, const float* __restrict__ kv,
                          const float* __restrict__ gam, const float* __restrict__ bet) {
    __shared__ float red[256];
    int row = blockIdx.x;
    const float* src;
    __nv_bfloat16 *dh, *dl;
    if (row < BB * NQ) {
        src = q + (size_t)row * DM;
        dh = g_qnh + (size_t)row * DM; dl = g_qnl + (size_t)row * DM;
    } else {
        int r = row - BB * NQ;
        src = kv + (size_t)r * DM;
        dh = g_kvnh + (size_t)r * DM; dl = g_kvnl + (size_t)r * DM;
    }
    int t = threadIdx.x;
    float4 x = ((const float4*)src)[t];
    red[t] = x.x + x.y + x.z + x.w;
    __syncthreads();
    for (int o = 128; o > 0; o >>= 1) { if (t < o) red[t] += red[t + o]; __syncthreads(); }
    float mu = red[0] * (1.0f / DM);
    __syncthreads();
    float dx = x.x - mu, dy = x.y - mu, dz = x.z - mu, dw = x.w - mu;
    red[t] = dx * dx + dy * dy + dz * dz + dw * dw;
    __syncthreads();
    for (int o = 128; o > 0; o >>= 1) { if (t < o) red[t] += red[t + o]; __syncthreads(); }
    float rstd = rsqrtf(red[0] * (1.0f / DM) + LNEPS);
    float4 g4 = ((const float4*)gam)[t];
    float4 b4 = ((const float4*)bet)[t];
    float o0 = dx * rstd * g4.x + b4.x;
    float o1 = dy * rstd * g4.y + b4.y;
    float o2 = dz * rstd * g4.z + b4.z;
    float o3 = dw * rstd * g4.w + b4.w;
    __nv_bfloat16 h[4], l[4];
    split_bf16(o0, h[0], l[0]); split_bf16(o1, h[1], l[1]);
    split_bf16(o2, h[2], l[2]); split_bf16(o3, h[3], l[3]);
    *(uint2*)(dh + 4 * t) = *(uint2*)h;
    *(uint2*)(dl + 4 * t) = *(uint2*)l;
}

// ---------------- weight transpose + bf16 split ----------------
__global__ void wconv_kernel(const float* __restrict__ W,
                             __nv_bfloat16* __restrict__ Th, __nv_bfloat16* __restrict__ Tl) {
    __shared__ float tile[32][33];
    int bx = blockIdx.x * 32;  // n
    int by = blockIdx.y * 32;  // k
    int tx = threadIdx.x, ty = threadIdx.y;
#pragma unroll
    for (int i = 0; i < 32; i += 8)
        tile[ty + i][tx] = W[(size_t)(by + ty + i) * DM + bx + tx];
    __syncthreads();
#pragma unroll
    for (int i = 0; i < 32; i += 8) {
        float v = tile[tx][ty + i];
        __nv_bfloat16 h, l;
        split_bf16(v, h, l);
        Th[(size_t)(bx + ty + i) * DM + by + tx] = h;
        Tl[(size_t)(bx + ty + i) * DM + by + tx] = l;
    }
}

// ---------------- V fp32 [b,kv,h,d] -> transposed split [bh][d][kv] bf16 --------
__global__ void vconv_kernel() {
    __shared__ float tile[32][33];
    int bh = blockIdx.z;
    int b = bh >> 4, h = bh & 15;
    int kv0 = blockIdx.x * 32, d0 = blockIdx.y * 32;
    int tx = threadIdx.x, ty = threadIdx.y;
#pragma unroll
    for (int i = 0; i < 32; i += 8)
        tile[ty + i][tx] = g_V[(size_t)(b * NKV + kv0 + ty + i) * DM + h * DH + d0 + tx];
    __syncthreads();
#pragma unroll
    for (int i = 0; i < 32; i += 8) {
        float v = tile[tx][ty + i];   // = V[kv0+tx][d0+ty+i]
        __nv_bfloat16 h2, l2;
        split_bf16(v, h2, l2);
        size_t o = ((size_t)bh * DH + d0 + ty + i) * NKV + kv0 + tx;
        g_Vth[o] = h2; g_Vtl[o] = l2;
    }
}

// ---------------- ctx fp32 -> bf16 hi/lo ----------------
__global__ void ctxconv_kernel() {
    int i = blockIdx.x * 256 + threadIdx.x;
    float v = g_ctx[i];
    __nv_bfloat16 h, l;
    split_bf16(v, h, l);
    g_ctxh[i] = h; g_ctxl[i] = l;
}

// ================= HMMA GEMM: C[M,1024] = (Ah+Al)@(Bh+Bl)^T + bias ==============
#define GS_AH 0
#define GS_AL 16384
#define GS_BH 32768
#define GS_BL 49152
#define GS_TOTAL 65536

__global__ __launch_bounds__(256, 2) void gemm_mma(
    const __nv_bfloat16* __restrict__ Ah, const __nv_bfloat16* __restrict__ Al,
    const __nv_bfloat16* __restrict__ Bh, const __nv_bfloat16* __restrict__ Bl,
    const float* __restrict__ bias, float* __restrict__ C,
    __nv_bfloat16* __restrict__ Ch, __nv_bfloat16* __restrict__ Cl) {
    extern __shared__ char smem[];
    uint32_t sb = smem_u32(smem);
    int t = threadIdx.x, lane = t & 31, wid = t >> 5;
    int wm = wid & 1, wn = wid >> 1;
    int m0 = blockIdx.y * 128, n0 = blockIdx.x * 128;

    float acc[4][4][4];
#pragma unroll
    for (int i = 0; i < 4; i++)
#pragma unroll
        for (int j = 0; j < 4; j++)
#pragma unroll
            for (int k = 0; k < 4; k++) acc[i][j][k] = 0.0f;

    for (int kt = 0; kt < 16; kt++) {
        int kg = kt * 64;
        if (kt > 0) __syncthreads();
#pragma unroll
        for (int i = 0; i < 4; i++) {
            int id = i * 256 + t;
            int r = id >> 3, c8 = id & 7;
            uint32_t off = (uint32_t)(r * 128 + ((c8 ^ (r & 7)) << 4));
            *(uint4*)(smem + GS_AH + off) = *(const uint4*)(Ah + (size_t)(m0 + r) * DM + kg + c8 * 8);
            *(uint4*)(smem + GS_AL + off) = *(const uint4*)(Al + (size_t)(m0 + r) * DM + kg + c8 * 8);
            *(uint4*)(smem + GS_BH + off) = *(const uint4*)(Bh + (size_t)(n0 + r) * DM + kg + c8 * 8);
            *(uint4*)(smem + GS_BL + off) = *(const uint4*)(Bl + (size_t)(n0 + r) * DM + kg + c8 * 8);
        }
        __syncthreads();
#pragma unroll
        for (int ks = 0; ks < 4; ks++) {
            int c0 = ks * 2;
            uint32_t bh[2][4], bl[2][4];
#pragma unroll
            for (int j = 0; j < 2; j++) {
                int rowb = wn * 32 + j * 16 + (lane & 15);
                int ch = c0 + (lane >> 4);
                uint32_t so = (uint32_t)(rowb * 128 + ((ch ^ (rowb & 7)) << 4));
                ldsm4(bh[j], sb + GS_BH + so);
                ldsm4(bl[j], sb + GS_BL + so);
            }
#pragma unroll
            for (int mi = 0; mi < 4; mi++) {
                int rowa = wm * 64 + mi * 16 + (lane & 15);
                int ch = c0 + (lane >> 4);
                uint32_t so = (uint32_t)(rowa * 128 + ((ch ^ (rowa & 7)) << 4));
                uint32_t ah[4], al[4];
                ldsm4(ah, sb + GS_AH + so);
                ldsm4(al, sb + GS_AL + so);
#pragma unroll
                for (int ni = 0; ni < 4; ni++) {
                    int j = ni >> 1, s = ni & 1;
                    mma16816(acc[mi][ni], ah, bh[j][s], bh[j][s + 2]);
                    mma16816(acc[mi][ni], ah, bl[j][s], bl[j][s + 2]);
                    mma16816(acc[mi][ni], al, bh[j][s], bh[j][s + 2]);
                }
            }
        }
    }

#pragma unroll
    for (int mi = 0; mi < 4; mi++) {
#pragma unroll
        for (int ni = 0; ni < 4; ni++) {
            int m = m0 + wm * 64 + mi * 16 + (lane >> 2);
            int n = n0 + wn * 32 + ni * 8 + (lane & 3) * 2;
            float2 bv = *(const float2*)(bias + n);
            float2 v0 = make_float2(acc[mi][ni][0] + bv.x, acc[mi][ni][1] + bv.y);
            float2 v1 = make_float2(acc[mi][ni][2] + bv.x, acc[mi][ni][3] + bv.y);
            if (C) {
                *(float2*)(C + (size_t)m * DM + n) = v0;
                *(float2*)(C + (size_t)(m + 8) * DM + n) = v1;
            }
            if (Ch) {
                __nv_bfloat16 h0, l0, h1, l1;
                split_bf16(v0.x, h0, l0); split_bf16(v0.y, h1, l1);
                *(__nv_bfloat162*)(Ch + (size_t)m * DM + n) = __nv_bfloat162(h0, h1);
                *(__nv_bfloat162*)(Cl + (size_t)m * DM + n) = __nv_bfloat162(l0, l1);
                split_bf16(v1.x, h0, l0); split_bf16(v1.y, h1, l1);
                *(__nv_bfloat162*)(Ch + (size_t)(m + 8) * DM + n) = __nv_bfloat162(h0, h1);
                *(__nv_bfloat162*)(Cl + (size_t)(m + 8) * DM + n) = __nv_bfloat162(l0, l1);
            }
        }
    }
}

// ================= qk HMMA: attn[bh][q][k] = mask ? (Q.K)*SCALE : -inf =========
// per (ktile, qtile, bh): A = Q[128q][64d], B = K[128k][64d], 3 bf16 products.
__global__ __launch_bounds__(256, 2) void qk_mma(float* __restrict__ attn) {
    extern __shared__ char smem[];
    uint32_t sb = smem_u32(smem);
    const int SA_H = 0, SA_L = 16384, SB_H = 32768, SB_L = 49152;
    int t = threadIdx.x, lane = t & 31, wid = t >> 5;
    int wm = wid & 1, wn = wid >> 1;
    int bhead = blockIdx.z;
    int b = bhead >> 4, h = bhead & 15;
    int q0 = blockIdx.y * 128, k0 = blockIdx.x * 128;

    // load tiles: rows 128, 8 chunks of 16B (64 bf16 per row)
#pragma unroll
    for (int i = 0; i < 4; i++) {
        int id = i * 256 + t;
        int r = id >> 3, c8 = id & 7;
        uint32_t off = (uint32_t)(r * 128 + ((c8 ^ (r & 7)) << 4));
        size_t qa = (size_t)(b * NQ + q0 + r) * DM + h * DH + c8 * 8;
        size_t ka = (size_t)(b * NKV + k0 + r) * DM + h * DH + c8 * 8;
        *(uint4*)(smem + SA_H + off) = *(const uint4*)(g_Qh + qa);
        *(uint4*)(smem + SA_L + off) = *(const uint4*)(g_Ql + qa);
        *(uint4*)(smem + SB_H + off) = *(const uint4*)(g_Kh + ka);
        *(uint4*)(smem + SB_L + off) = *(const uint4*)(g_Kl + ka);
    }
    __syncthreads();

    float acc[4][4][4];
#pragma unroll
    for (int i = 0; i < 4; i++)
#pragma unroll
        for (int j = 0; j < 4; j++)
#pragma unroll
            for (int k = 0; k < 4; k++) acc[i][j][k] = 0.0f;

#pragma unroll
    for (int ks = 0; ks < 4; ks++) {
        int c0 = ks * 2;
        uint32_t bh2[2][4], bl2[2][4];
#pragma unroll
        for (int j = 0; j < 2; j++) {
            int rowb = wn * 32 + j * 16 + (lane & 15);
            int ch = c0 + (lane >> 4);
            uint32_t so = (uint32_t)(rowb * 128 + ((ch ^ (rowb & 7)) << 4));
            ldsm4(bh2[j], sb + SB_H + so);
            ldsm4(bl2[j], sb + SB_L + so);
        }
#pragma unroll
        for (int mi = 0; mi < 4; mi++) {
            int rowa = wm * 64 + mi * 16 + (lane & 15);
            int ch = c0 + (lane >> 4);
            uint32_t so = (uint32_t)(rowa * 128 + ((ch ^ (rowa & 7)) << 4));
            uint32_t ah[4], al[4];
            ldsm4(ah, sb + SA_H + so);
            ldsm4(al, sb + SA_L + so);
#pragma unroll
            for (int ni = 0; ni < 4; ni++) {
                int j = ni >> 1, s = ni & 1;
                mma16816(acc[mi][ni], ah, bh2[j][s], bh2[j][s + 2]);
                mma16816(acc[mi][ni], ah, bl2[j][s], bl2[j][s + 2]);
                mma16816(acc[mi][ni], al, bh2[j][s], bh2[j][s + 2]);
            }
        }
    }

#pragma unroll
    for (int mi = 0; mi < 4; mi++) {
#pragma unroll
        for (int ni = 0; ni < 4; ni++) {
            int m = q0 + wm * 64 + mi * 16 + (lane >> 2);
            int n = k0 + wn * 32 + ni * 8 + (lane & 3) * 2;
            float m0v = g_mask[b * NKV + n], m1v = g_mask[b * NKV + n + 1];
            float2 v0, v1;
            v0.x = m0v != 0.0f ? acc[mi][ni][0] * SCALE : -INFINITY;
            v0.y = m1v != 0.0f ? acc[mi][ni][1] * SCALE : -INFINITY;
            v1.x = m0v != 0.0f ? acc[mi][ni][2] * SCALE : -INFINITY;
            v1.y = m1v != 0.0f ? acc[mi][ni][3] * SCALE : -INFINITY;
            *(float2*)(attn + ((size_t)bhead * NQ + m) * NKV + n) = v0;
            *(float2*)(attn + ((size_t)bhead * NQ + m + 8) * NKV + n) = v1;
        }
    }
}

// ================= rpe HMMA: attn[bh][q][k] += SCALE * Qh . rpe_bf16 ===========
// per (ktile, q): M=32 bh, N=128 k, K=64 d. 4 warps, warp n-span 32.
__global__ __launch_bounds__(128) void rpe_mma(const float* __restrict__ rpe,
                                               float* __restrict__ attn) {
    __shared__ __nv_bfloat16 Rp[128 * 64];   // [k][d] swizzled, 16KB
    __shared__ __nv_bfloat16 Qs[32 * 64];    // [bh][d] swizzled, 4KB
    uint32_t sRp = smem_u32(Rp), sQs = smem_u32(Qs);
    int t = threadIdx.x, lane = t & 31, w = t >> 5;
    int q = blockIdx.y;
    int k0 = blockIdx.x * 128;

    // load rpe tile fp32 -> bf16 (128 rows x 16 float4)
    const float4* gr = (const float4*)(rpe + ((size_t)q * NKV + k0) * DH);
#pragma unroll
    for (int i = 0; i < 16; i++) {
        int idx = i * 128 + t;
        int r = idx >> 4, c4 = idx & 15;
        float4 v = gr[idx];
        __nv_bfloat16 bv[4] = {__float2bfloat16_rn(v.x), __float2bfloat16_rn(v.y),
                               __float2bfloat16_rn(v.z), __float2bfloat16_rn(v.w)};
        int c8 = c4 >> 1, half = c4 & 1;
        *(uint2*)((char*)Rp + r * 128 + ((c8 ^ (r & 7)) << 4) + half * 8) = *(uint2*)bv;
    }
    // load Q rows for 32 bh (32 rows x 8 chunks)
#pragma unroll
    for (int i = 0; i < 2; i++) {
        int id = i * 128 + t;
        int r = id >> 3, c8 = id & 7;
        int b = r >> 4, h = r & 15;
        *(uint4*)((char*)Qs + r * 128 + ((c8 ^ (r & 7)) << 4)) =
            *(const uint4*)(g_Qh + (size_t)(b * NQ + q) * DM + h * DH + c8 * 8);
    }
    __syncthreads();

    float acc[2][4][4];
#pragma unroll
    for (int i = 0; i < 2; i++)
#pragma unroll
        for (int j = 0; j < 4; j++)
#pragma unroll
            for (int k = 0; k < 4; k++) acc[i][j][k] = 0.0f;

#pragma unroll
    for (int ks = 0; ks < 4; ks++) {
        int c0 = ks * 2;
        uint32_t bf[2][4];
#pragma unroll
        for (int j = 0; j < 2; j++) {
            int rowb = w * 32 + j * 16 + (lane & 15);
            int ch = c0 + (lane >> 4);
            ldsm4(bf[j], sRp + (uint32_t)(rowb * 128 + ((ch ^ (rowb & 7)) << 4)));
        }
#pragma unroll
        for (int mi = 0; mi < 2; mi++) {
            int rowa = mi * 16 + (lane & 15);
            int ch = c0 + (lane >> 4);
            uint32_t af[4];
            ldsm4(af, sQs + (uint32_t)(rowa * 128 + ((ch ^ (rowa & 7)) << 4)));
#pragma unroll
            for (int ni = 0; ni < 4; ni++) {
                int j = ni >> 1, s = ni & 1;
                mma16816(acc[mi][ni], af, bf[j][s], bf[j][s + 2]);
            }
        }
    }

#pragma unroll
    for (int mi = 0; mi < 2; mi++) {
#pragma unroll
        for (int ni = 0; ni < 4; ni++) {
            int m = mi * 16 + (lane >> 2);           // bh
            int n = k0 + w * 32 + ni * 8 + (lane & 3) * 2;
            float* p0 = attn + ((size_t)m * NQ + q) * NKV + n;
            float* p1 = attn + ((size_t)(m + 8) * NQ + q) * NKV + n;
            float2 c0v = *(float2*)p0, c1v = *(float2*)p1;
            c0v.x += SCALE * acc[mi][ni][0]; c0v.y += SCALE * acc[mi][ni][1];
            c1v.x += SCALE * acc[mi][ni][2]; c1v.y += SCALE * acc[mi][ni][3];
            *(float2*)p0 = c0v;
            *(float2*)p1 = c1v;
        }
    }
}

// ---------------- softmax (in place) + bf16 hi/lo prob writes ----------------
__global__ void softmax_kernel(float* __restrict__ attn) {
    __shared__ float red[256];
    size_t row = blockIdx.x;
    float4* p = (float4*)(attn + row * (size_t)NKV);
    int t = threadIdx.x;
    float4 v1 = p[t], v2 = p[t + 256];
    float m = fmaxf(fmaxf(fmaxf(v1.x, v1.y), fmaxf(v1.z, v1.w)),
                    fmaxf(fmaxf(v2.x, v2.y), fmaxf(v2.z, v2.w)));
    red[t] = m;
    __syncthreads();
    for (int o = 128; o > 0; o >>= 1) { if (t < o) red[t] = fmaxf(red[t], red[t + o]); __syncthreads(); }
    float M = red[0];
    __syncthreads();
    v1.x = __expf(v1.x - M); v1.y = __expf(v1.y - M); v1.z = __expf(v1.z - M); v1.w = __expf(v1.w - M);
    v2.x = __expf(v2.x - M); v2.y = __expf(v2.y - M); v2.z = __expf(v2.z - M); v2.w = __expf(v2.w - M);
    float s = v1.x + v1.y + v1.z + v1.w + v2.x + v2.y + v2.z + v2.w;
    red[t] = s;
    __syncthreads();
    for (int o = 128; o > 0; o >>= 1) { if (t < o) red[t] += red[t + o]; __syncthreads(); }
    float inv = 1.0f / red[0];
    v1.x *= inv; v1.y *= inv; v1.z *= inv; v1.w *= inv;
    v2.x *= inv; v2.y *= inv; v2.z *= inv; v2.w *= inv;
    p[t] = v1;
    p[t + 256] = v2;
    // bf16 hi/lo split for AV
    __nv_bfloat16 h[8], l[8];
    split_bf16(v1.x, h[0], l[0]); split_bf16(v1.y, h[1], l[1]);
    split_bf16(v1.z, h[2], l[2]); split_bf16(v1.w, h[3], l[3]);
    split_bf16(v2.x, h[4], l[4]); split_bf16(v2.y, h[5], l[5]);
    split_bf16(v2.z, h[6], l[6]); split_bf16(v2.w, h[7], l[7]);
    *(uint2*)(g_ah + row * NKV + 4 * t) = *(uint2*)h;
    *(uint2*)(g_al + row * NKV + 4 * t) = *(uint2*)l;
    *(uint2*)(g_ah + row * NKV + 1024 + 4 * t) = *(uint2*)(h + 4);
    *(uint2*)(g_al + row * NKV + 1024 + 4 * t) = *(uint2*)(l + 4);
}

// ================= av HMMA: ctx[bh][q][d] = attn @ V ===========================
// per (qtile, bh): M=128 q, N=64 d, K=2048 streamed in 64-chunks.
__global__ __launch_bounds__(256, 2) void av_mma() {
    extern __shared__ char smem[];
    uint32_t sb = smem_u32(smem);
    const int SA_H = 0, SA_L = 16384, SB_H = 32768, SB_L = 40960;  // B tiles 8KB each
    int t = threadIdx.x, lane = t & 31, wid = t >> 5;
    int wm = wid >> 1, wn = wid & 1;
    int bhead = blockIdx.y;
    int b = bhead >> 4, h = bhead & 15;
    int q0 = blockIdx.x * 128;

    float acc[2][4][4];
#pragma unroll
    for (int i = 0; i < 2; i++)
#pragma unroll
        for (int j = 0; j < 4; j++)
#pragma unroll
            for (int k = 0; k < 4; k++) acc[i][j][k] = 0.0f;

    for (int kt = 0; kt < 32; kt++) {
        int kg = kt * 64;
        if (kt > 0) __syncthreads();
        // A: attn 128 rows x 8 chunks
#pragma unroll
        for (int i = 0; i < 4; i++) {
            int id = i * 256 + t;
            int r = id >> 3, c8 = id & 7;
            uint32_t off = (uint32_t)(r * 128 + ((c8 ^ (r & 7)) << 4));
            size_t ga = ((size_t)bhead * NQ + q0 + r) * NKV + kg + c8 * 8;
            *(uint4*)(smem + SA_H + off) = *(const uint4*)(g_ah + ga);
            *(uint4*)(smem + SA_L + off) = *(const uint4*)(g_al + ga);
        }
        // B: Vt 64 rows x 8 chunks
        {
            int id = t, r = id >> 3, c8 = id & 7;   // 256 threads cover 256 of 512 chunks
#pragma unroll
            for (int i = 0; i < 2; i++) {
                int id2 = i * 256 + t;
                r = id2 >> 3; c8 = id2 & 7;
                uint32_t off = (uint32_t)(r * 128 + ((c8 ^ (r & 7)) << 4));
                size_t gv = ((size_t)bhead * DH + r) * NKV + kg + c8 * 8;
                *(uint4*)(smem + SB_H + off) = *(const uint4*)(g_Vth + gv);
                *(uint4*)(smem + SB_L + off) = *(const uint4*)(g_Vtl + gv);
            }
        }
        __syncthreads();
#pragma unroll
        for (int ks = 0; ks < 4; ks++) {
            int c0 = ks * 2;
            uint32_t bh2[2][4], bl2[2][4];
#pragma unroll
            for (int j = 0; j < 2; j++) {
                int rowb = wn * 32 + j * 16 + (lane & 15);
                int ch = c0 + (lane >> 4);
                uint32_t so = (uint32_t)(rowb * 128 + ((ch ^ (rowb & 7)) << 4));
                ldsm4(bh2[j], sb + SB_H + so);
                ldsm4(bl2[j], sb + SB_L + so);
            }
#pragma unroll
            for (int mi = 0; mi < 2; mi++) {
                int rowa = wm * 32 + mi * 16 + (lane & 15);
                int ch = c0 + (lane >> 4);
                uint32_t so = (uint32_t)(rowa * 128 + ((ch ^ (rowa & 7)) << 4));
                uint32_t ah[4], al[4];
                ldsm4(ah, sb + SA_H + so);
                ldsm4(al, sb + SA_L + so);
#pragma unroll
                for (int ni = 0; ni < 4; ni++) {
                    int j = ni >> 1, s = ni & 1;
                    mma16816(acc[mi][ni], ah, bh2[j][s], bh2[j][s + 2]);
                    mma16816(acc[mi][ni], ah, bl2[j][s], bl2[j][s + 2]);
                    mma16816(acc[mi][ni], al, bh2[j][s], bh2[j][s + 2]);
                }
            }
        }
    }

#pragma unroll
    for (int mi = 0; mi < 2; mi++) {
#pragma unroll
        for (int ni = 0; ni < 4; ni++) {
            int m = q0 + wm * 32 + mi * 16 + (lane >> 2);
            int n = wn * 32 + ni * 8 + (lane & 3) * 2;
            *(float2*)(g_ctx + (size_t)(b * NQ + m) * DM + h * DH + n) =
                make_float2(acc[mi][ni][0], acc[mi][ni][1]);
            *(float2*)(g_ctx + (size_t)(b * NQ + m + 8) * DM + h * DH + n) =
                make_float2(acc[mi][ni][2], acc[mi][ni][3]);
        }
    }
}

// ---------------- launch ----------------
extern "C" void kernel_launch(void* const* d_in, const int* in_sizes, int n_in,
                              void* d_out, int out_size) {
    const float* q = (const float*)d_in[0];
    const float* kv = (const float*)d_in[1];
    const unsigned char* mask = (const unsigned char*)d_in[2];
    const float* rpe = (const float*)d_in[3];
    const float* Wq = (const float*)d_in[4];
    const float* bq = (const float*)d_in[5];
    const float* Wk = (const float*)d_in[6];
    const float* bk = (const float*)d_in[7];
    const float* Wv = (const float*)d_in[8];
    const float* bv = (const float*)d_in[9];
    const float* Wo = (const float*)d_in[10];
    const float* bo = (const float*)d_in[11];
    const float* lg = (const float*)d_in[12];
    const float* lb = (const float*)d_in[13];

    float* out = (float*)d_out;
    const size_t ATT = (size_t)BB * NH * NQ * NKV;
    const size_t OUTN = (size_t)BB * NQ * DM;
    float* attn;
    if ((size_t)out_size >= ATT + OUTN) {
        attn = out + ((size_t)out_size - ATT);
    } else {
        void* p;
        cudaGetSymbolAddress(&p, g_attn_fallback);
        attn = (float*)p;
    }

#define SYMF(sym) ([]{ void* p; cudaGetSymbolAddress(&p, sym); return (float*)p; }())
#define SYMB(sym) ([]{ void* p; cudaGetSymbolAddress(&p, sym); return (__nv_bfloat16*)p; }())
    float* p_Q = SYMF(g_Q);
    float* p_V = SYMF(g_V);
    __nv_bfloat16* p_qnh = SYMB(g_qnh);   __nv_bfloat16* p_qnl = SYMB(g_qnl);
    __nv_bfloat16* p_kvnh = SYMB(g_kvnh); __nv_bfloat16* p_kvnl = SYMB(g_kvnl);
    __nv_bfloat16* p_Wqh = SYMB(g_Wqh);   __nv_bfloat16* p_Wql = SYMB(g_Wql);
    __nv_bfloat16* p_Wkh = SYMB(g_Wkh);   __nv_bfloat16* p_Wkl = SYMB(g_Wkl);
    __nv_bfloat16* p_Wvh = SYMB(g_Wvh);   __nv_bfloat16* p_Wvl = SYMB(g_Wvl);
    __nv_bfloat16* p_Woh = SYMB(g_Woh);   __nv_bfloat16* p_Wol = SYMB(g_Wol);
    __nv_bfloat16* p_ctxh = SYMB(g_ctxh); __nv_bfloat16* p_ctxl = SYMB(g_ctxl);
    __nv_bfloat16* p_Qh = SYMB(g_Qh);     __nv_bfloat16* p_Ql = SYMB(g_Ql);
    __nv_bfloat16* p_Kh = SYMB(g_Kh);     __nv_bfloat16* p_Kl = SYMB(g_Kl);

    cudaFuncSetAttribute(gemm_mma, cudaFuncAttributeMaxDynamicSharedMemorySize, GS_TOTAL);
    cudaFuncSetAttribute(qk_mma, cudaFuncAttributeMaxDynamicSharedMemorySize, 65536);
    cudaFuncSetAttribute(av_mma, cudaFuncAttributeMaxDynamicSharedMemorySize, 49152);

    mask_kernel<<<1, 256>>>(mask);
    ln_kernel<<<BB * NQ + BB * NKV, 256>>>(q, kv, lg, lb);

    dim3 wt(32, 8);
    dim3 wg(32, 32);
    wconv_kernel<<<wg, wt>>>(Wq, p_Wqh, p_Wql);
    wconv_kernel<<<wg, wt>>>(Wk, p_Wkh, p_Wkl);
    wconv_kernel<<<wg, wt>>>(Wv, p_Wvh, p_Wvl);
    wconv_kernel<<<wg, wt>>>(Wo, p_Woh, p_Wol);

    gemm_mma<<<dim3(8, 16), 256, GS_TOTAL>>>(p_qnh, p_qnl, p_Wqh, p_Wql, bq, p_Q, p_Qh, p_Ql);
    gemm_mma<<<dim3(8, 32), 256, GS_TOTAL>>>(p_kvnh, p_kvnl, p_Wkh, p_Wkl, bk, nullptr, p_Kh, p_Kl);
    gemm_mma<<<dim3(8, 32), 256, GS_TOTAL>>>(p_kvnh, p_kvnl, p_Wvh, p_Wvl, bv, p_V, nullptr, nullptr);

    vconv_kernel<<<dim3(NKV / 32, 2, BB * NH), wt>>>();

    qk_mma<<<dim3(NKV / 128, NQ / 128, BB * NH), 256, 65536>>>(attn);
    rpe_mma<<<dim3(NKV / 128, NQ), 128>>>(rpe, attn);
    softmax_kernel<<<BB * NH * NQ, 256>>>(attn);
    av_mma<<<dim3(NQ / 128, BB * NH), 256, 49152>>>();

    ctxconv_kernel<<<(BB * NQ * NH * DH) / 256, 256>>>();
    gemm_mma<<<dim3(8, 16), 256, GS_TOTAL>>>(p_ctxh, p_ctxl, p_Woh, p_Wol, bo, out, nullptr, nullptr);
}